// round 9
// baseline (speedup 1.0000x reference)
#include <cuda_runtime.h>
#include <math.h>
#include <stdint.h>

// Problem constants
#define D_MODEL 1024
#define N_HEADS 16
#define HD      64
#define BATCH   4
#define SEQ     2048
#define BH      (BATCH * N_HEADS)   // 64
#define M_TOK   (BATCH * SEQ)       // 8192

// Scratch (device globals: allocation-free per harness rules)
__device__ float    g_Q[(size_t)BH * SEQ * HD];
__device__ float    g_K[(size_t)BH * SEQ * HD];
__device__ float    g_V[(size_t)BH * SEQ * HD];
__device__ uint32_t g_Xp[(size_t)M_TOK * D_MODEL];        // x, packed tf32 A-frag
__device__ uint32_t g_Yp[(size_t)M_TOK * D_MODEL];        // attn out, packed tf32 A-frag
__device__ uint32_t g_Wpa[(size_t)3 * D_MODEL * D_MODEL]; // W_attn^T packed tf32 B-frag
__device__ uint32_t g_Wpp[(size_t)D_MODEL * D_MODEL];     // W_proj^T packed tf32 B-frag

// ---------------------------------------------------------------------------
// Helpers (base-target ISA; sm_80+)
// ---------------------------------------------------------------------------
__device__ __forceinline__ uint32_t f2tf32(float f) {
    uint32_t r;
    asm("cvt.rna.tf32.f32 %0, %1;" : "=r"(r) : "f"(f));
    return r;
}
__device__ __forceinline__ void mma_tf32(float d[4], const uint32_t a[4],
                                         const uint32_t b[2]) {
    asm volatile(
        "mma.sync.aligned.m16n8k8.row.col.f32.tf32.tf32.f32 "
        "{%0,%1,%2,%3}, {%4,%5,%6,%7}, {%8,%9}, {%0,%1,%2,%3};"
        : "+f"(d[0]), "+f"(d[1]), "+f"(d[2]), "+f"(d[3])
        : "r"(a[0]), "r"(a[1]), "r"(a[2]), "r"(a[3]), "r"(b[0]), "r"(b[1]));
}
__device__ __forceinline__ uint32_t smem_u32(const void* p) {
    uint32_t a;
    asm("{ .reg .u64 t; cvta.to.shared.u64 t, %1; cvt.u32.u64 %0, t; }"
        : "=r"(a) : "l"(p));
    return a;
}
#define CP16(dst, src) \
    asm volatile("cp.async.cg.shared.global [%0], [%1], 16;" \
                 :: "r"(dst), "l"(src) : "memory")
#define CPCOMMIT() asm volatile("cp.async.commit_group;" ::: "memory")
#define CPWAIT1()  asm volatile("cp.async.wait_group 1;" ::: "memory")
#define CPWAIT0()  asm volatile("cp.async.wait_group 0;" ::: "memory")

// ---------------------------------------------------------------------------
// Packing kernels (unchanged from Round 8).
// ---------------------------------------------------------------------------
__global__ void pack_a(const float* __restrict__ X, uint32_t* __restrict__ Xp)
{
    const int i    = blockIdx.x * 256 + threadIdx.x;   // uint4 index
    const int lane = i & 31, kc = (i >> 5) & 3, slab = (i >> 7) & 31, mb = i >> 12;
    const int g = lane >> 2, t = lane & 3;
    const float* p = X + ((size_t)(mb * 16 + g)) * D_MODEL + slab * 32 + kc * 8 + t;
    uint4 o;
    o.x = f2tf32(p[0]);
    o.y = f2tf32(p[8 * D_MODEL]);
    o.z = f2tf32(p[4]);
    o.w = f2tf32(p[8 * D_MODEL + 4]);
    *(uint4*)&Xp[(size_t)i * 4] = o;
}

__global__ void pack_b(const float* __restrict__ W, uint32_t* __restrict__ Wp, int N)
{
    const int i    = blockIdx.x * 256 + threadIdx.x;
    const int lane = i & 31, kp = (i >> 5) & 1, slab = (i >> 6) & 31, nb = i >> 11;
    const int g = lane >> 2, t = lane & 3;
    const int n  = nb * 8 + g;
    const int k0 = slab * 32 + kp * 16 + t;
    const float* p = W + (size_t)k0 * N + n;
    uint4 o;
    o.x = f2tf32(p[0]);
    o.y = f2tf32(p[(size_t)4 * N]);
    o.z = f2tf32(p[(size_t)8 * N]);
    o.w = f2tf32(p[(size_t)12 * N]);
    *(uint4*)&Wp[(size_t)i * 4] = o;
}

// ---------------------------------------------------------------------------
// TF32 GEMM, cp.async 2-stage, packed operands (unchanged from Round 8).
// ---------------------------------------------------------------------------
#define GEMM_SMEM 65536

template <int MODE>
__global__ void __launch_bounds__(256, 2)
gemm_mma(const uint32_t* __restrict__ Apk, const uint32_t* __restrict__ Bpk,
         const float* __restrict__ bias, float* __restrict__ Cout)
{
    constexpr int NS = 32;
    extern __shared__ uint32_t sm[];
    const int tid  = threadIdx.x;
    const int wid  = tid >> 5;
    const int lane = tid & 31;
    const int g    = lane >> 2;
    const int tig  = lane & 3;
    const int m0   = blockIdx.y * 128;
    const int n0   = blockIdx.x * 128;
    const int mb0  = m0 >> 4;
    const int nb0  = n0 >> 3;
    const uint32_t smb = smem_u32(sm);

    float acc[2][8][4];
#pragma unroll
    for (int mf = 0; mf < 2; mf++)
#pragma unroll
        for (int nf = 0; nf < 8; nf++)
#pragma unroll
            for (int r = 0; r < 4; r++) acc[mf][nf][r] = 0.0f;

    uint32_t asrc[4], bsrc[4], adst[4], bdst[4];
#pragma unroll
    for (int c = 0; c < 4; c++) {
        const int ci = c * 256 + tid;
        asrc[c] = (uint32_t)(mb0 + (ci >> 7)) * 16384u + (uint32_t)(ci & 127) * 4u;
        bsrc[c] = (uint32_t)(nb0 + (ci >> 6)) * 8192u  + (uint32_t)(ci & 63) * 4u;
        adst[c] = smb + (uint32_t)ci * 16u;
        bdst[c] = smb + 16384u + (uint32_t)ci * 16u;
    }

    auto issue = [&](int s, int buf) {
        const uint32_t so = (uint32_t)buf * 32768u;
#pragma unroll
        for (int c = 0; c < 4; c++)
            CP16(adst[c] + so, (const void*)(Apk + asrc[c] + (uint32_t)s * 512u));
#pragma unroll
        for (int c = 0; c < 4; c++)
            CP16(bdst[c] + so, (const void*)(Bpk + bsrc[c] + (uint32_t)s * 256u));
        CPCOMMIT();
    };

    issue(0, 0);

    const int wm4 = (wid & 3) * 2;
    const int wn8 = (wid >> 2) * 8;

    for (int s = 0; s < NS; s++) {
        if (s + 1 < NS) { issue(s + 1, (s + 1) & 1); CPWAIT1(); }
        else            { CPWAIT0(); }
        __syncthreads();

        const uint32_t* Ab = sm + (uint32_t)(s & 1) * 8192u;
        const uint32_t* Bb = Ab + 4096;

#pragma unroll
        for (int kp = 0; kp < 2; kp++) {
            uint4 af[2][2];
#pragma unroll
            for (int mf = 0; mf < 2; mf++)
#pragma unroll
                for (int h = 0; h < 2; h++)
                    af[mf][h] = *(const uint4*)&Ab[(((wm4 + mf) * 4 + kp * 2 + h) * 32 + lane) * 4];
#pragma unroll
            for (int nf = 0; nf < 8; nf++) {
                const uint4 bv = *(const uint4*)&Bb[(((wn8 + nf) * 2 + kp) * 32 + lane) * 4];
#pragma unroll
                for (int h = 0; h < 2; h++) {
                    uint32_t b2[2];
                    b2[0] = h ? bv.z : bv.x;
                    b2[1] = h ? bv.w : bv.y;
                    mma_tf32(acc[0][nf], (const uint32_t*)&af[0][h], b2);
                    mma_tf32(acc[1][nf], (const uint32_t*)&af[1][h], b2);
                }
            }
        }
        __syncthreads();
    }

#pragma unroll
    for (int mf = 0; mf < 2; mf++) {
        const int row0 = m0 + (wid & 3) * 32 + mf * 16 + g;
#pragma unroll
        for (int nf = 0; nf < 8; nf++) {
            const int col = n0 + (wid >> 2) * 64 + nf * 8 + 2 * tig;
            const float2 bv = *(const float2*)(bias + col);
            float2 v0 = make_float2(acc[mf][nf][0] + bv.x, acc[mf][nf][1] + bv.y);
            float2 v1 = make_float2(acc[mf][nf][2] + bv.x, acc[mf][nf][3] + bv.y);
            if (MODE == 0) {
                *(float2*)(Cout + (size_t)row0 * D_MODEL + col)       = v0;
                *(float2*)(Cout + (size_t)(row0 + 8) * D_MODEL + col) = v1;
            } else {
                const int which = col >> 10;
                const int c2    = col & 1023;
                const int h     = c2 >> 6;
                const int d     = c2 & 63;
                float* dst = (which == 0) ? g_Q : (which == 1) ? g_K : g_V;
                const int bb0 = row0 >> 11, t0 = row0 & 2047;
                const int r1  = row0 + 8;
                const int bb1 = r1 >> 11,   t1 = r1 & 2047;
                *(float2*)(dst + (((size_t)(bb0 * N_HEADS + h)) * SEQ + t0) * HD + d) = v0;
                *(float2*)(dst + (((size_t)(bb1 * N_HEADS + h)) * SEQ + t1) * HD + d) = v1;
            }
        }
    }
}

// ---------------------------------------------------------------------------
// Flash attention (Round-9):
//  * Q staged ONCE in packed A-fragment layout -> A loads are 1x LDS.128.
//  * K staging: register transpose -> 4x STS.128 per thread (was 16 STS.32).
//  * V staging: key-strided LDGs so each thread owns complete B-fragment
//    uint4s -> 4x STS.128 per thread (was 16 scattered STS.32).
// Math order and all cvt points identical to Round 8 (rel_err canary).
// ---------------------------------------------------------------------------
#define KPB 132
#define PACK_U32 (32 * KPB)
#define QROWS 256
#define QP_U32 (QROWS * HD)              // 16384 u32 = 64KB
#define FLASH_SMEM ((QP_U32 + 2 * PACK_U32) * 4)

__global__ void __launch_bounds__(256, 1)
flash_mma()
{
    extern __shared__ uint32_t fsm[];
    uint32_t* Qp = fsm;                  // packed A-frag: [(mb*8+kc8)*32+lane]*4
    uint32_t* Kp = Qp + QP_U32;          // packed K B-frags
    uint32_t* Vp = Kp + PACK_U32;        // packed V B-frags
    uint4* Qp4 = (uint4*)Qp;

    const int tid  = threadIdx.x;
    const int wid  = tid >> 5;
    const int lane = tid & 31;
    const int g    = lane >> 2;
    const int tig  = lane & 3;
    const int qt   = (int)gridDim.x - 1 - (int)blockIdx.x;
    const int bh   = blockIdx.y;
    const int q0   = qt * QROWS;

    const float QSCALE = 0.125f * 1.44269504f;

    // Stage Q packed: thread covers rows (16mb+qg, 16mb+8+qg), k-half khalf*32.
    {
        const int mb = tid >> 4, qg = (tid >> 1) & 7, khalf = tid & 1;
        const float* r0p = g_Q + ((size_t)bh * SEQ + q0 + mb * 16 + qg) * HD + khalf * 32;
        const float* r1p = r0p + 8 * HD;
#pragma unroll
        for (int kc = 0; kc < 4; kc++) {
            const int kb = kc * 8;
            float4 x0 = *(const float4*)(r0p + kb);
            float4 x1 = *(const float4*)(r0p + kb + 4);
            float4 y0 = *(const float4*)(r1p + kb);
            float4 y1 = *(const float4*)(r1p + kb + 4);
            const int base = (mb * 8 + khalf * 4 + kc) * 32 + qg * 4;
            Qp4[base + 0] = make_uint4(f2tf32(x0.x * QSCALE), f2tf32(y0.x * QSCALE),
                                       f2tf32(x1.x * QSCALE), f2tf32(y1.x * QSCALE));
            Qp4[base + 1] = make_uint4(f2tf32(x0.y * QSCALE), f2tf32(y0.y * QSCALE),
                                       f2tf32(x1.y * QSCALE), f2tf32(y1.y * QSCALE));
            Qp4[base + 2] = make_uint4(f2tf32(x0.z * QSCALE), f2tf32(y0.z * QSCALE),
                                       f2tf32(x1.z * QSCALE), f2tf32(y1.z * QSCALE));
            Qp4[base + 3] = make_uint4(f2tf32(x0.w * QSCALE), f2tf32(y0.w * QSCALE),
                                       f2tf32(x1.w * QSCALE), f2tf32(y1.w * QSCALE));
        }
    }

    float mrow[2][2], lrow[2][2], Of[2][8][4];
#pragma unroll
    for (int mf = 0; mf < 2; mf++) {
        mrow[mf][0] = mrow[mf][1] = -1e30f;
        lrow[mf][0] = lrow[mf][1] = 0.0f;
#pragma unroll
        for (int nf = 0; nf < 8; nf++)
#pragma unroll
            for (int r = 0; r < 4; r++) Of[mf][nf][r] = 0.0f;
    }

    const int nt = qt * 4 + 4;

    // K staging map: skey = tid>>2 (0..63), 16 d at (tid&3)*16
    const int skey = tid >> 2;
    const int skp  = tid & 3;
    const int sg   = skey & 7;
    const int snf  = skey >> 3;
    uint4* kdst = (uint4*)&Kp[(snf * 4 + skp) * KPB + sg * 16];
    const float* kbase = g_K + (size_t)bh * SEQ * HD + (size_t)skey * HD + skp * 16;

    // V staging map: thread owns keys 16*vkp + vt + 4j (j=0..3), d range [vd0, vd0+4)
    const int vt  = tid & 3;
    const int vkp = (tid >> 2) & 3;
    const int vd0 = (tid >> 4) * 4;
    const float* vbase[4];
#pragma unroll
    for (int j = 0; j < 4; j++)
        vbase[j] = g_V + (size_t)bh * SEQ * HD
                 + (size_t)(vkp * 16 + vt + 4 * j) * HD + vd0;

    // Prefetch tile 0
    float pk[4][4], pv[4][4];
#pragma unroll
    for (int i = 0; i < 4; i++) {
        *(float4*)pk[i] = *(const float4*)(kbase + i * 4);
        *(float4*)pv[i] = *(const float4*)vbase[i];
    }

    for (int kt = 0; kt < nt; kt++) {
        // Store staged K: 4x STS.128 (register transpose)
#pragma unroll
        for (int t = 0; t < 4; t++)
            kdst[t] = make_uint4(f2tf32(pk[0][t]), f2tf32(pk[1][t]),
                                 f2tf32(pk[2][t]), f2tf32(pk[3][t]));
        // Store staged V: 4x STS.128 (each uint4 = one B-frag lane word)
#pragma unroll
        for (int w = 0; w < 4; w++) {
            const int d = vd0 + w;
            *(uint4*)&Vp[((d >> 3) * 4 + vkp) * KPB + ((d & 7) * 4 + vt) * 4] =
                make_uint4(f2tf32(pv[0][w]), f2tf32(pv[1][w]),
                           f2tf32(pv[2][w]), f2tf32(pv[3][w]));
        }
        __syncthreads();

        // Issue next tile's LDGs; they land during compute.
        if (kt + 1 < nt) {
            const size_t off = (size_t)(kt + 1) * 64 * HD;
#pragma unroll
            for (int i = 0; i < 4; i++) {
                *(float4*)pk[i] = *(const float4*)(kbase + off + i * 4);
                *(float4*)pv[i] = *(const float4*)(vbase[i] + off);
            }
        }

        // ---- S = Q K^T ----
        float sacc[2][8][4];
#pragma unroll
        for (int mf = 0; mf < 2; mf++)
#pragma unroll
            for (int nf = 0; nf < 8; nf++)
#pragma unroll
                for (int r = 0; r < 4; r++) sacc[mf][nf][r] = 0.0f;

#pragma unroll
        for (int kp = 0; kp < 4; kp++) {
            uint4 aq[2][2];
#pragma unroll
            for (int mf = 0; mf < 2; mf++)
#pragma unroll
                for (int h = 0; h < 2; h++)
                    aq[mf][h] = Qp4[((wid * 2 + mf) * 8 + kp * 2 + h) * 32 + lane];
#pragma unroll
            for (int half = 0; half < 2; half++) {
                uint4 kb[4];
#pragma unroll
                for (int i = 0; i < 4; i++)
                    kb[i] = *(const uint4*)&Kp[((half * 4 + i) * 4 + kp) * KPB + lane * 4];
#pragma unroll
                for (int h = 0; h < 2; h++)
#pragma unroll
                    for (int i = 0; i < 4; i++) {
                        uint32_t b[2];
                        b[0] = h ? kb[i].z : kb[i].x;
                        b[1] = h ? kb[i].w : kb[i].y;
                        mma_tf32(sacc[0][half * 4 + i], (const uint32_t*)&aq[0][h], b);
                        mma_tf32(sacc[1][half * 4 + i], (const uint32_t*)&aq[1][h], b);
                    }
            }
        }

        // Causal mask
        if (kt >= nt - 4) {
            const int n0 = kt * 64;
#pragma unroll
            for (int mf = 0; mf < 2; mf++) {
                const int r0g = q0 + wid * 32 + mf * 16 + g;
#pragma unroll
                for (int nf = 0; nf < 8; nf++) {
                    const int c0 = n0 + nf * 8 + 2 * tig;
                    if (c0     > r0g)     sacc[mf][nf][0] = -1e30f;
                    if (c0 + 1 > r0g)     sacc[mf][nf][1] = -1e30f;
                    if (c0     > r0g + 8) sacc[mf][nf][2] = -1e30f;
                    if (c0 + 1 > r0g + 8) sacc[mf][nf][3] = -1e30f;
                }
            }
        }

        // ---- Online softmax ----
        uint32_t P0[2][8], P1[2][8], P2[2][8], P3[2][8];
#pragma unroll
        for (int mf = 0; mf < 2; mf++) {
            float rm0 = -1e30f, rm1 = -1e30f;
#pragma unroll
            for (int nf = 0; nf < 8; nf++) {
                rm0 = fmaxf(rm0, fmaxf(sacc[mf][nf][0], sacc[mf][nf][1]));
                rm1 = fmaxf(rm1, fmaxf(sacc[mf][nf][2], sacc[mf][nf][3]));
            }
            rm0 = fmaxf(rm0, __shfl_xor_sync(0xffffffffu, rm0, 1));
            rm0 = fmaxf(rm0, __shfl_xor_sync(0xffffffffu, rm0, 2));
            rm1 = fmaxf(rm1, __shfl_xor_sync(0xffffffffu, rm1, 1));
            rm1 = fmaxf(rm1, __shfl_xor_sync(0xffffffffu, rm1, 2));

            const float nm0 = fmaxf(mrow[mf][0], rm0);
            const float nm1 = fmaxf(mrow[mf][1], rm1);
            const float al0 = exp2f(mrow[mf][0] - nm0);
            const float al1 = exp2f(mrow[mf][1] - nm1);
            mrow[mf][0] = nm0; mrow[mf][1] = nm1;

            float rs0 = 0.0f, rs1 = 0.0f;
#pragma unroll
            for (int nf = 0; nf < 8; nf++) {
                const float p0 = exp2f(sacc[mf][nf][0] - nm0);
                const float p1 = exp2f(sacc[mf][nf][1] - nm0);
                const float p2 = exp2f(sacc[mf][nf][2] - nm1);
                const float p3 = exp2f(sacc[mf][nf][3] - nm1);
                rs0 += p0 + p1;
                rs1 += p2 + p3;
                P0[mf][nf] = f2tf32(p0); P1[mf][nf] = f2tf32(p1);
                P2[mf][nf] = f2tf32(p2); P3[mf][nf] = f2tf32(p3);
            }
            rs0 += __shfl_xor_sync(0xffffffffu, rs0, 1);
            rs0 += __shfl_xor_sync(0xffffffffu, rs0, 2);
            rs1 += __shfl_xor_sync(0xffffffffu, rs1, 1);
            rs1 += __shfl_xor_sync(0xffffffffu, rs1, 2);
            lrow[mf][0] = lrow[mf][0] * al0 + rs0;
            lrow[mf][1] = lrow[mf][1] * al1 + rs1;

#pragma unroll
            for (int nf = 0; nf < 8; nf++) {
                Of[mf][nf][0] *= al0; Of[mf][nf][1] *= al0;
                Of[mf][nf][2] *= al1; Of[mf][nf][3] *= al1;
            }
        }

        // ---- O += P V ----
        const int srcA = (lane & 28) | (tig >> 1);
        const int srcB = srcA + 2;
        const bool hi  = (tig & 1);
#pragma unroll
        for (int kp = 0; kp < 4; kp++) {
            uint32_t ap[2][2][4];
#pragma unroll
            for (int mf = 0; mf < 2; mf++)
#pragma unroll
                for (int h = 0; h < 2; h++) {
                    const int kc = kp * 2 + h;
                    uint32_t x0 = __shfl_sync(0xffffffffu, P0[mf][kc], srcA);
                    uint32_t x1 = __shfl_sync(0xffffffffu, P1[mf][kc], srcA);
                    uint32_t y0 = __shfl_sync(0xffffffffu, P2[mf][kc], srcA);
                    uint32_t y1 = __shfl_sync(0xffffffffu, P3[mf][kc], srcA);
                    uint32_t z0 = __shfl_sync(0xffffffffu, P0[mf][kc], srcB);
                    uint32_t z1 = __shfl_sync(0xffffffffu, P1[mf][kc], srcB);
                    uint32_t w0 = __shfl_sync(0xffffffffu, P2[mf][kc], srcB);
                    uint32_t w1 = __shfl_sync(0xffffffffu, P3[mf][kc], srcB);
                    ap[mf][h][0] = hi ? x1 : x0;
                    ap[mf][h][1] = hi ? y1 : y0;
                    ap[mf][h][2] = hi ? z1 : z0;
                    ap[mf][h][3] = hi ? w1 : w0;
                }
#pragma unroll
            for (int half = 0; half < 2; half++) {
                uint4 vb[4];
#pragma unroll
                for (int i = 0; i < 4; i++)
                    vb[i] = *(const uint4*)&Vp[((half * 4 + i) * 4 + kp) * KPB + lane * 4];
#pragma unroll
                for (int h = 0; h < 2; h++)
#pragma unroll
                    for (int i = 0; i < 4; i++) {
                        uint32_t b[2];
                        b[0] = h ? vb[i].z : vb[i].x;
                        b[1] = h ? vb[i].w : vb[i].y;
                        mma_tf32(Of[0][half * 4 + i], ap[0][h], b);
                        mma_tf32(Of[1][half * 4 + i], ap[1][h], b);
                    }
            }
        }
        __syncthreads();
    }

    // Epilogue: write packed tf32 A-fragment g_Yp (quad-shuffle transform).
    const int b = bh >> 4;
    const int h = bh & 15;
    const int srcA = (lane & 28) | (tig >> 1);
    const int srcB = srcA + 2;
    const bool hi  = (tig & 1);
#pragma unroll
    for (int mf = 0; mf < 2; mf++) {
        const float inv0 = 1.0f / lrow[mf][0];
        const float inv1 = 1.0f / lrow[mf][1];
        const int mb = (b * SEQ + q0 + wid * 32 + mf * 16) >> 4;
#pragma unroll
        for (int j = 0; j < 8; j++) {
            const float n0f = Of[mf][j][0] * inv0;
            const float n1f = Of[mf][j][1] * inv0;
            const float n2f = Of[mf][j][2] * inv1;
            const float n3f = Of[mf][j][3] * inv1;
            const float x0 = __shfl_sync(0xffffffffu, n0f, srcA);
            const float x1 = __shfl_sync(0xffffffffu, n1f, srcA);
            const float y0 = __shfl_sync(0xffffffffu, n2f, srcA);
            const float y1 = __shfl_sync(0xffffffffu, n3f, srcA);
            const float z0 = __shfl_sync(0xffffffffu, n0f, srcB);
            const float z1 = __shfl_sync(0xffffffffu, n1f, srcB);
            const float w0 = __shfl_sync(0xffffffffu, n2f, srcB);
            const float w1 = __shfl_sync(0xffffffffu, n3f, srcB);
            uint4 o;
            o.x = f2tf32(hi ? x1 : x0);
            o.y = f2tf32(hi ? y1 : y0);
            o.z = f2tf32(hi ? z1 : z0);
            o.w = f2tf32(hi ? w1 : w0);
            const int slab = 2 * h + (j >> 2);
            const int kc   = j & 3;
            *(uint4*)&g_Yp[(((size_t)mb * 32 + slab) * 4 + kc) * 128 + lane * 4] = o;
        }
    }
}

// ---------------------------------------------------------------------------
extern "C" void kernel_launch(void* const* d_in, const int* in_sizes, int n_in,
                              void* d_out, int out_size)
{
    const float* x      = (const float*)d_in[0];
    const float* W_attn = (const float*)d_in[1];
    const float* b_attn = (const float*)d_in[2];
    const float* W_proj = (const float*)d_in[3];
    const float* b_proj = (const float*)d_in[4];
    float* out = (float*)d_out;

    cudaFuncSetAttribute(gemm_mma<1>, cudaFuncAttributeMaxDynamicSharedMemorySize, GEMM_SMEM);
    cudaFuncSetAttribute(gemm_mma<0>, cudaFuncAttributeMaxDynamicSharedMemorySize, GEMM_SMEM);
    cudaFuncSetAttribute(flash_mma, cudaFuncAttributeMaxDynamicSharedMemorySize, FLASH_SMEM);

    uint32_t* xp;  cudaGetSymbolAddress((void**)&xp,  g_Xp);
    uint32_t* yp;  cudaGetSymbolAddress((void**)&yp,  g_Yp);
    uint32_t* wpa; cudaGetSymbolAddress((void**)&wpa, g_Wpa);
    uint32_t* wpp; cudaGetSymbolAddress((void**)&wpp, g_Wpp);

    // 0) Pack operands to fragment-layout tf32
    pack_a<<<(M_TOK * D_MODEL / 4) / 256, 256>>>(x, xp);
    pack_b<<<(3 * D_MODEL * D_MODEL / 4) / 256, 256>>>(W_attn, wpa, 3 * D_MODEL);
    pack_b<<<(D_MODEL * D_MODEL / 4) / 256, 256>>>(W_proj, wpp, D_MODEL);

    // 1) QKV projection -> g_Q/g_K/g_V
    {
        dim3 grid(3 * D_MODEL / 128, M_TOK / 128);  // (24, 64)
        gemm_mma<1><<<grid, 256, GEMM_SMEM>>>(xp, wpa, b_attn, nullptr);
    }
    // 2) Causal flash attention -> g_Yp (packed tf32)
    {
        dim3 grid(SEQ / QROWS, BH);  // (8, 64)
        flash_mma<<<grid, 256, FLASH_SMEM>>>();
    }
    // 3) Output projection -> d_out
    {
        dim3 grid(D_MODEL / 128, M_TOK / 128);  // (8, 64)
        gemm_mma<0><<<grid, 256, GEMM_SMEM>>>(yp, wpp, b_proj, out);
    }
}

// round 10
// speedup vs baseline: 1.0559x; 1.0559x over previous
#include <cuda_runtime.h>
#include <math.h>
#include <stdint.h>

// Problem constants
#define D_MODEL 1024
#define N_HEADS 16
#define HD      64
#define BATCH   4
#define SEQ     2048
#define BH      (BATCH * N_HEADS)   // 64
#define M_TOK   (BATCH * SEQ)       // 8192

// Scratch (device globals: allocation-free per harness rules)
__device__ float    g_Q[(size_t)BH * SEQ * HD];
__device__ float    g_K[(size_t)BH * SEQ * HD];
__device__ float    g_V[(size_t)BH * SEQ * HD];
__device__ uint32_t g_Xp[(size_t)M_TOK * D_MODEL];        // x, packed tf32 A-frag
__device__ uint32_t g_Yp[(size_t)M_TOK * D_MODEL];        // attn out, packed tf32 A-frag
__device__ uint32_t g_Wpa[(size_t)3 * D_MODEL * D_MODEL]; // W_attn^T packed tf32 B-frag
__device__ uint32_t g_Wpp[(size_t)D_MODEL * D_MODEL];     // W_proj^T packed tf32 B-frag
__device__ uint32_t g_Qp[(size_t)BH * SEQ * HD];          // Q packed tf32 A-frag (scaled)
__device__ uint32_t g_Kp[(size_t)BH * SEQ * HD];          // K packed tf32 B-frag
__device__ uint32_t g_Vp[(size_t)BH * SEQ * HD];          // V packed tf32 B-frag (n=d)

// ---------------------------------------------------------------------------
// Helpers (base-target ISA; sm_80+)
// ---------------------------------------------------------------------------
__device__ __forceinline__ uint32_t f2tf32(float f) {
    uint32_t r;
    asm("cvt.rna.tf32.f32 %0, %1;" : "=r"(r) : "f"(f));
    return r;
}
__device__ __forceinline__ void mma_tf32(float d[4], const uint32_t a[4],
                                         const uint32_t b[2]) {
    asm volatile(
        "mma.sync.aligned.m16n8k8.row.col.f32.tf32.tf32.f32 "
        "{%0,%1,%2,%3}, {%4,%5,%6,%7}, {%8,%9}, {%0,%1,%2,%3};"
        : "+f"(d[0]), "+f"(d[1]), "+f"(d[2]), "+f"(d[3])
        : "r"(a[0]), "r"(a[1]), "r"(a[2]), "r"(a[3]), "r"(b[0]), "r"(b[1]));
}
__device__ __forceinline__ uint32_t smem_u32(const void* p) {
    uint32_t a;
    asm("{ .reg .u64 t; cvta.to.shared.u64 t, %1; cvt.u32.u64 %0, t; }"
        : "=r"(a) : "l"(p));
    return a;
}
#define CP16(dst, src) \
    asm volatile("cp.async.cg.shared.global [%0], [%1], 16;" \
                 :: "r"(dst), "l"(src) : "memory")
#define CPCOMMIT() asm volatile("cp.async.commit_group;" ::: "memory")
#define CPWAIT1()  asm volatile("cp.async.wait_group 1;" ::: "memory")
#define CPWAIT0()  asm volatile("cp.async.wait_group 0;" ::: "memory")

// ---------------------------------------------------------------------------
// GEMM packing kernels (unchanged from Round 8).
// ---------------------------------------------------------------------------
__global__ void pack_a(const float* __restrict__ X, uint32_t* __restrict__ Xp)
{
    const int i    = blockIdx.x * 256 + threadIdx.x;   // uint4 index
    const int lane = i & 31, kc = (i >> 5) & 3, slab = (i >> 7) & 31, mb = i >> 12;
    const int g = lane >> 2, t = lane & 3;
    const float* p = X + ((size_t)(mb * 16 + g)) * D_MODEL + slab * 32 + kc * 8 + t;
    uint4 o;
    o.x = f2tf32(p[0]);
    o.y = f2tf32(p[8 * D_MODEL]);
    o.z = f2tf32(p[4]);
    o.w = f2tf32(p[8 * D_MODEL + 4]);
    *(uint4*)&Xp[(size_t)i * 4] = o;
}

__global__ void pack_b(const float* __restrict__ W, uint32_t* __restrict__ Wp, int N)
{
    const int i    = blockIdx.x * 256 + threadIdx.x;
    const int lane = i & 31, kp = (i >> 5) & 1, slab = (i >> 6) & 31, nb = i >> 11;
    const int g = lane >> 2, t = lane & 3;
    const int n  = nb * 8 + g;
    const int k0 = slab * 32 + kp * 16 + t;
    const float* p = W + (size_t)k0 * N + n;
    uint4 o;
    o.x = f2tf32(p[0]);
    o.y = f2tf32(p[(size_t)4 * N]);
    o.z = f2tf32(p[(size_t)8 * N]);
    o.w = f2tf32(p[(size_t)12 * N]);
    *(uint4*)&Wp[(size_t)i * 4] = o;
}

// ---------------------------------------------------------------------------
// Flash packing kernels: g_Q/g_K/g_V (fp32, head-major) -> fragment-layout tf32.
// Q A-frag (QSCALE folded): uint4 i -> lane(5) | c(3) | mb(4) | qt(3) | bh(6).
//   rows r0 = qt*256 + mb*16 + g, r1 = r0+8; k-chunk 8c.
// K B-frag: uint4 i -> lane(5) | blk(5) | kt(5) | bh(6); nf=blk>>2, kp=blk&3.
//   key = kt*64 + 8nf + g; d = 16kp + t (+4,+8,+12).
// V B-frag (n=d, k=key): d = 8*(blk>>2)+g; key = kt*64 + 16*(blk&3) + t (+4..).
// ---------------------------------------------------------------------------
__global__ void pack_q(const float* __restrict__ Q, uint32_t* __restrict__ Qp)
{
    const float QSCALE = 0.125f * 1.44269504f;
    const int i    = blockIdx.x * 256 + threadIdx.x;
    const int lane = i & 31, c = (i >> 5) & 7, mb = (i >> 8) & 15;
    const int qt   = (i >> 12) & 7, bh = i >> 15;
    const int g = lane >> 2, t = lane & 3;
    const float* r0 = Q + ((size_t)bh * SEQ + qt * 256 + mb * 16 + g) * HD + c * 8;
    const float* r1 = r0 + 8 * HD;
    uint4 o;
    o.x = f2tf32(r0[t]     * QSCALE);
    o.y = f2tf32(r1[t]     * QSCALE);
    o.z = f2tf32(r0[t + 4] * QSCALE);
    o.w = f2tf32(r1[t + 4] * QSCALE);
    *(uint4*)&Qp[(size_t)i * 4] = o;
}

__global__ void pack_k(const float* __restrict__ K, uint32_t* __restrict__ Kp)
{
    const int i    = blockIdx.x * 256 + threadIdx.x;
    const int lane = i & 31, blk = (i >> 5) & 31, kt = (i >> 10) & 31, bh = i >> 15;
    const int g = lane >> 2, t = lane & 3;
    const int nf = blk >> 2, kp = blk & 3;
    const int key = kt * 64 + 8 * nf + g;
    const float* p = K + ((size_t)bh * SEQ + key) * HD + kp * 16 + t;
    uint4 o;
    o.x = f2tf32(p[0]);
    o.y = f2tf32(p[4]);
    o.z = f2tf32(p[8]);
    o.w = f2tf32(p[12]);
    *(uint4*)&Kp[(size_t)i * 4] = o;
}

__global__ void pack_v(const float* __restrict__ V, uint32_t* __restrict__ Vp)
{
    const int i    = blockIdx.x * 256 + threadIdx.x;
    const int lane = i & 31, blk = (i >> 5) & 31, kt = (i >> 10) & 31, bh = i >> 15;
    const int g = lane >> 2, t = lane & 3;
    const int d  = 8 * (blk >> 2) + g;
    const int key0 = kt * 64 + 16 * (blk & 3) + t;
    const float* p = V + ((size_t)bh * SEQ + key0) * HD + d;
    uint4 o;
    o.x = f2tf32(p[0]);
    o.y = f2tf32(p[(size_t)4 * HD]);
    o.z = f2tf32(p[(size_t)8 * HD]);
    o.w = f2tf32(p[(size_t)12 * HD]);
    *(uint4*)&Vp[(size_t)i * 4] = o;
}

// ---------------------------------------------------------------------------
// TF32 GEMM, cp.async 2-stage, packed operands (unchanged from Round 8).
// ---------------------------------------------------------------------------
#define GEMM_SMEM 65536

template <int MODE>
__global__ void __launch_bounds__(256, 2)
gemm_mma(const uint32_t* __restrict__ Apk, const uint32_t* __restrict__ Bpk,
         const float* __restrict__ bias, float* __restrict__ Cout)
{
    constexpr int NS = 32;
    extern __shared__ uint32_t sm[];
    const int tid  = threadIdx.x;
    const int wid  = tid >> 5;
    const int lane = tid & 31;
    const int g    = lane >> 2;
    const int tig  = lane & 3;
    const int m0   = blockIdx.y * 128;
    const int n0   = blockIdx.x * 128;
    const int mb0  = m0 >> 4;
    const int nb0  = n0 >> 3;
    const uint32_t smb = smem_u32(sm);

    float acc[2][8][4];
#pragma unroll
    for (int mf = 0; mf < 2; mf++)
#pragma unroll
        for (int nf = 0; nf < 8; nf++)
#pragma unroll
            for (int r = 0; r < 4; r++) acc[mf][nf][r] = 0.0f;

    uint32_t asrc[4], bsrc[4], adst[4], bdst[4];
#pragma unroll
    for (int c = 0; c < 4; c++) {
        const int ci = c * 256 + tid;
        asrc[c] = (uint32_t)(mb0 + (ci >> 7)) * 16384u + (uint32_t)(ci & 127) * 4u;
        bsrc[c] = (uint32_t)(nb0 + (ci >> 6)) * 8192u  + (uint32_t)(ci & 63) * 4u;
        adst[c] = smb + (uint32_t)ci * 16u;
        bdst[c] = smb + 16384u + (uint32_t)ci * 16u;
    }

    auto issue = [&](int s, int buf) {
        const uint32_t so = (uint32_t)buf * 32768u;
#pragma unroll
        for (int c = 0; c < 4; c++)
            CP16(adst[c] + so, (const void*)(Apk + asrc[c] + (uint32_t)s * 512u));
#pragma unroll
        for (int c = 0; c < 4; c++)
            CP16(bdst[c] + so, (const void*)(Bpk + bsrc[c] + (uint32_t)s * 256u));
        CPCOMMIT();
    };

    issue(0, 0);

    const int wm4 = (wid & 3) * 2;
    const int wn8 = (wid >> 2) * 8;

    for (int s = 0; s < NS; s++) {
        if (s + 1 < NS) { issue(s + 1, (s + 1) & 1); CPWAIT1(); }
        else            { CPWAIT0(); }
        __syncthreads();

        const uint32_t* Ab = sm + (uint32_t)(s & 1) * 8192u;
        const uint32_t* Bb = Ab + 4096;

#pragma unroll
        for (int kp = 0; kp < 2; kp++) {
            uint4 af[2][2];
#pragma unroll
            for (int mf = 0; mf < 2; mf++)
#pragma unroll
                for (int h = 0; h < 2; h++)
                    af[mf][h] = *(const uint4*)&Ab[(((wm4 + mf) * 4 + kp * 2 + h) * 32 + lane) * 4];
#pragma unroll
            for (int nf = 0; nf < 8; nf++) {
                const uint4 bv = *(const uint4*)&Bb[(((wn8 + nf) * 2 + kp) * 32 + lane) * 4];
#pragma unroll
                for (int h = 0; h < 2; h++) {
                    uint32_t b2[2];
                    b2[0] = h ? bv.z : bv.x;
                    b2[1] = h ? bv.w : bv.y;
                    mma_tf32(acc[0][nf], (const uint32_t*)&af[0][h], b2);
                    mma_tf32(acc[1][nf], (const uint32_t*)&af[1][h], b2);
                }
            }
        }
        __syncthreads();
    }

#pragma unroll
    for (int mf = 0; mf < 2; mf++) {
        const int row0 = m0 + (wid & 3) * 32 + mf * 16 + g;
#pragma unroll
        for (int nf = 0; nf < 8; nf++) {
            const int col = n0 + (wid >> 2) * 64 + nf * 8 + 2 * tig;
            const float2 bv = *(const float2*)(bias + col);
            float2 v0 = make_float2(acc[mf][nf][0] + bv.x, acc[mf][nf][1] + bv.y);
            float2 v1 = make_float2(acc[mf][nf][2] + bv.x, acc[mf][nf][3] + bv.y);
            if (MODE == 0) {
                *(float2*)(Cout + (size_t)row0 * D_MODEL + col)       = v0;
                *(float2*)(Cout + (size_t)(row0 + 8) * D_MODEL + col) = v1;
            } else {
                const int which = col >> 10;
                const int c2    = col & 1023;
                const int h     = c2 >> 6;
                const int d     = c2 & 63;
                float* dst = (which == 0) ? g_Q : (which == 1) ? g_K : g_V;
                const int bb0 = row0 >> 11, t0 = row0 & 2047;
                const int r1  = row0 + 8;
                const int bb1 = r1 >> 11,   t1 = r1 & 2047;
                *(float2*)(dst + (((size_t)(bb0 * N_HEADS + h)) * SEQ + t0) * HD + d) = v0;
                *(float2*)(dst + (((size_t)(bb1 * N_HEADS + h)) * SEQ + t1) * HD + d) = v1;
            }
        }
    }
}

// ---------------------------------------------------------------------------
// Flash attention (Round-10): all operands pre-packed tf32 in gmem.
// Q staged once via cp.async (64KB); K/V per 64-key tile via 2-stage cp.async
// pipeline (16KB each, contiguous copies). No cvt / transpose in mainloop.
// Smem: Q 64KB + 2 stages x 32KB = 128KB. Layouts contiguous (stride 128) --
// copy pattern == load pattern, conflict-free.
// ---------------------------------------------------------------------------
#define QROWS 256
#define QP_U32 (QROWS * HD)              // 16384 u32 = 64KB
#define KVT_U32 4096                     // one K or V tile = 16KB
#define FLASH_SMEM ((QP_U32 + 2 * 2 * KVT_U32) * 4)   // 131072

__global__ void __launch_bounds__(256, 1)
flash_mma()
{
    extern __shared__ uint32_t fsm[];
    uint4* Qp4 = (uint4*)fsm;            // packed A-frag
    const uint32_t smb = smem_u32(fsm);

    const int tid  = threadIdx.x;
    const int wid  = tid >> 5;
    const int lane = tid & 31;
    const int g    = lane >> 2;
    const int tig  = lane & 3;
    const int qt   = (int)gridDim.x - 1 - (int)blockIdx.x;
    const int bh   = blockIdx.y;
    const int q0   = qt * QROWS;
    const int nt   = qt * 4 + 4;

    const uint32_t* qg = g_Qp + ((size_t)bh * 8 + qt) * QP_U32;
    const uint32_t* kg = g_Kp + (size_t)bh * 32 * KVT_U32;
    const uint32_t* vg = g_Vp + (size_t)bh * 32 * KVT_U32;

    // Q copy: 16 x CP16 per thread, one group.
#pragma unroll
    for (int c = 0; c < 16; c++)
        CP16(smb + (uint32_t)(c * 256 + tid) * 16u,
             (const void*)(qg + (size_t)(c * 256 + tid) * 4));
    CPCOMMIT();

    auto issueKV = [&](int kt, int buf) {
        const uint32_t so = smb + (uint32_t)(QP_U32 + buf * 2 * KVT_U32) * 4u;
        const uint32_t* ks = kg + (size_t)kt * KVT_U32;
        const uint32_t* vs = vg + (size_t)kt * KVT_U32;
#pragma unroll
        for (int c = 0; c < 4; c++)
            CP16(so + (uint32_t)(c * 256 + tid) * 16u,
                 (const void*)(ks + (size_t)(c * 256 + tid) * 4));
#pragma unroll
        for (int c = 0; c < 4; c++)
            CP16(so + (uint32_t)KVT_U32 * 4u + (uint32_t)(c * 256 + tid) * 16u,
                 (const void*)(vs + (size_t)(c * 256 + tid) * 4));
        CPCOMMIT();
    };

    issueKV(0, 0);

    float mrow[2][2], lrow[2][2], Of[2][8][4];
#pragma unroll
    for (int mf = 0; mf < 2; mf++) {
        mrow[mf][0] = mrow[mf][1] = -1e30f;
        lrow[mf][0] = lrow[mf][1] = 0.0f;
#pragma unroll
        for (int nf = 0; nf < 8; nf++)
#pragma unroll
            for (int r = 0; r < 4; r++) Of[mf][nf][r] = 0.0f;
    }

    for (int kt = 0; kt < nt; kt++) {
        if (kt + 1 < nt) { issueKV(kt + 1, (kt + 1) & 1); CPWAIT1(); }
        else             { CPWAIT0(); }
        __syncthreads();

        const uint32_t* Kps = fsm + QP_U32 + (kt & 1) * 2 * KVT_U32;
        const uint32_t* Vps = Kps + KVT_U32;

        // ---- S = Q K^T ----
        float sacc[2][8][4];
#pragma unroll
        for (int mf = 0; mf < 2; mf++)
#pragma unroll
            for (int nf = 0; nf < 8; nf++)
#pragma unroll
                for (int r = 0; r < 4; r++) sacc[mf][nf][r] = 0.0f;

#pragma unroll
        for (int kp = 0; kp < 4; kp++) {
            uint4 aq[2][2];
#pragma unroll
            for (int mf = 0; mf < 2; mf++)
#pragma unroll
                for (int h = 0; h < 2; h++)
                    aq[mf][h] = Qp4[((wid * 2 + mf) * 8 + kp * 2 + h) * 32 + lane];
#pragma unroll
            for (int half = 0; half < 2; half++) {
                uint4 kb[4];
#pragma unroll
                for (int i = 0; i < 4; i++)
                    kb[i] = *(const uint4*)&Kps[(((half * 4 + i) * 4 + kp) * 32 + lane) * 4];
#pragma unroll
                for (int h = 0; h < 2; h++)
#pragma unroll
                    for (int i = 0; i < 4; i++) {
                        uint32_t b[2];
                        b[0] = h ? kb[i].z : kb[i].x;
                        b[1] = h ? kb[i].w : kb[i].y;
                        mma_tf32(sacc[0][half * 4 + i], (const uint32_t*)&aq[0][h], b);
                        mma_tf32(sacc[1][half * 4 + i], (const uint32_t*)&aq[1][h], b);
                    }
            }
        }

        // Causal mask
        if (kt >= nt - 4) {
            const int n0 = kt * 64;
#pragma unroll
            for (int mf = 0; mf < 2; mf++) {
                const int r0g = q0 + wid * 32 + mf * 16 + g;
#pragma unroll
                for (int nf = 0; nf < 8; nf++) {
                    const int c0 = n0 + nf * 8 + 2 * tig;
                    if (c0     > r0g)     sacc[mf][nf][0] = -1e30f;
                    if (c0 + 1 > r0g)     sacc[mf][nf][1] = -1e30f;
                    if (c0     > r0g + 8) sacc[mf][nf][2] = -1e30f;
                    if (c0 + 1 > r0g + 8) sacc[mf][nf][3] = -1e30f;
                }
            }
        }

        // ---- Online softmax ----
        uint32_t P0[2][8], P1[2][8], P2[2][8], P3[2][8];
#pragma unroll
        for (int mf = 0; mf < 2; mf++) {
            float rm0 = -1e30f, rm1 = -1e30f;
#pragma unroll
            for (int nf = 0; nf < 8; nf++) {
                rm0 = fmaxf(rm0, fmaxf(sacc[mf][nf][0], sacc[mf][nf][1]));
                rm1 = fmaxf(rm1, fmaxf(sacc[mf][nf][2], sacc[mf][nf][3]));
            }
            rm0 = fmaxf(rm0, __shfl_xor_sync(0xffffffffu, rm0, 1));
            rm0 = fmaxf(rm0, __shfl_xor_sync(0xffffffffu, rm0, 2));
            rm1 = fmaxf(rm1, __shfl_xor_sync(0xffffffffu, rm1, 1));
            rm1 = fmaxf(rm1, __shfl_xor_sync(0xffffffffu, rm1, 2));

            const float nm0 = fmaxf(mrow[mf][0], rm0);
            const float nm1 = fmaxf(mrow[mf][1], rm1);
            const float al0 = exp2f(mrow[mf][0] - nm0);
            const float al1 = exp2f(mrow[mf][1] - nm1);
            mrow[mf][0] = nm0; mrow[mf][1] = nm1;

            float rs0 = 0.0f, rs1 = 0.0f;
#pragma unroll
            for (int nf = 0; nf < 8; nf++) {
                const float p0 = exp2f(sacc[mf][nf][0] - nm0);
                const float p1 = exp2f(sacc[mf][nf][1] - nm0);
                const float p2 = exp2f(sacc[mf][nf][2] - nm1);
                const float p3 = exp2f(sacc[mf][nf][3] - nm1);
                rs0 += p0 + p1;
                rs1 += p2 + p3;
                P0[mf][nf] = f2tf32(p0); P1[mf][nf] = f2tf32(p1);
                P2[mf][nf] = f2tf32(p2); P3[mf][nf] = f2tf32(p3);
            }
            rs0 += __shfl_xor_sync(0xffffffffu, rs0, 1);
            rs0 += __shfl_xor_sync(0xffffffffu, rs0, 2);
            rs1 += __shfl_xor_sync(0xffffffffu, rs1, 1);
            rs1 += __shfl_xor_sync(0xffffffffu, rs1, 2);
            lrow[mf][0] = lrow[mf][0] * al0 + rs0;
            lrow[mf][1] = lrow[mf][1] * al1 + rs1;

#pragma unroll
            for (int nf = 0; nf < 8; nf++) {
                Of[mf][nf][0] *= al0; Of[mf][nf][1] *= al0;
                Of[mf][nf][2] *= al1; Of[mf][nf][3] *= al1;
            }
        }

        // ---- O += P V ----
        const int srcA = (lane & 28) | (tig >> 1);
        const int srcB = srcA + 2;
        const bool hi  = (tig & 1);
#pragma unroll
        for (int kp = 0; kp < 4; kp++) {
            uint32_t ap[2][2][4];
#pragma unroll
            for (int mf = 0; mf < 2; mf++)
#pragma unroll
                for (int h = 0; h < 2; h++) {
                    const int kc = kp * 2 + h;
                    uint32_t x0 = __shfl_sync(0xffffffffu, P0[mf][kc], srcA);
                    uint32_t x1 = __shfl_sync(0xffffffffu, P1[mf][kc], srcA);
                    uint32_t y0 = __shfl_sync(0xffffffffu, P2[mf][kc], srcA);
                    uint32_t y1 = __shfl_sync(0xffffffffu, P3[mf][kc], srcA);
                    uint32_t z0 = __shfl_sync(0xffffffffu, P0[mf][kc], srcB);
                    uint32_t z1 = __shfl_sync(0xffffffffu, P1[mf][kc], srcB);
                    uint32_t w0 = __shfl_sync(0xffffffffu, P2[mf][kc], srcB);
                    uint32_t w1 = __shfl_sync(0xffffffffu, P3[mf][kc], srcB);
                    ap[mf][h][0] = hi ? x1 : x0;
                    ap[mf][h][1] = hi ? y1 : y0;
                    ap[mf][h][2] = hi ? z1 : z0;
                    ap[mf][h][3] = hi ? w1 : w0;
                }
#pragma unroll
            for (int half = 0; half < 2; half++) {
                uint4 vb[4];
#pragma unroll
                for (int i = 0; i < 4; i++)
                    vb[i] = *(const uint4*)&Vps[(((half * 4 + i) * 4 + kp) * 32 + lane) * 4];
#pragma unroll
                for (int h = 0; h < 2; h++)
#pragma unroll
                    for (int i = 0; i < 4; i++) {
                        uint32_t b[2];
                        b[0] = h ? vb[i].z : vb[i].x;
                        b[1] = h ? vb[i].w : vb[i].y;
                        mma_tf32(Of[0][half * 4 + i], ap[0][h], b);
                        mma_tf32(Of[1][half * 4 + i], ap[1][h], b);
                    }
            }
        }
        __syncthreads();   // all fragment reads done before buffer reuse
    }

    // Epilogue: write packed tf32 A-fragment g_Yp (quad-shuffle transform).
    const int b = bh >> 4;
    const int h = bh & 15;
    const int srcA = (lane & 28) | (tig >> 1);
    const int srcB = srcA + 2;
    const bool hi  = (tig & 1);
#pragma unroll
    for (int mf = 0; mf < 2; mf++) {
        const float inv0 = 1.0f / lrow[mf][0];
        const float inv1 = 1.0f / lrow[mf][1];
        const int mb = (b * SEQ + q0 + wid * 32 + mf * 16) >> 4;
#pragma unroll
        for (int j = 0; j < 8; j++) {
            const float n0f = Of[mf][j][0] * inv0;
            const float n1f = Of[mf][j][1] * inv0;
            const float n2f = Of[mf][j][2] * inv1;
            const float n3f = Of[mf][j][3] * inv1;
            const float x0 = __shfl_sync(0xffffffffu, n0f, srcA);
            const float x1 = __shfl_sync(0xffffffffu, n1f, srcA);
            const float y0 = __shfl_sync(0xffffffffu, n2f, srcA);
            const float y1 = __shfl_sync(0xffffffffu, n3f, srcA);
            const float z0 = __shfl_sync(0xffffffffu, n0f, srcB);
            const float z1 = __shfl_sync(0xffffffffu, n1f, srcB);
            const float w0 = __shfl_sync(0xffffffffu, n2f, srcB);
            const float w1 = __shfl_sync(0xffffffffu, n3f, srcB);
            uint4 o;
            o.x = f2tf32(hi ? x1 : x0);
            o.y = f2tf32(hi ? y1 : y0);
            o.z = f2tf32(hi ? z1 : z0);
            o.w = f2tf32(hi ? w1 : w0);
            const int slab = 2 * h + (j >> 2);
            const int kc   = j & 3;
            *(uint4*)&g_Yp[(((size_t)mb * 32 + slab) * 4 + kc) * 128 + lane * 4] = o;
        }
    }
}

// ---------------------------------------------------------------------------
extern "C" void kernel_launch(void* const* d_in, const int* in_sizes, int n_in,
                              void* d_out, int out_size)
{
    const float* x      = (const float*)d_in[0];
    const float* W_attn = (const float*)d_in[1];
    const float* b_attn = (const float*)d_in[2];
    const float* W_proj = (const float*)d_in[3];
    const float* b_proj = (const float*)d_in[4];
    float* out = (float*)d_out;

    cudaFuncSetAttribute(gemm_mma<1>, cudaFuncAttributeMaxDynamicSharedMemorySize, GEMM_SMEM);
    cudaFuncSetAttribute(gemm_mma<0>, cudaFuncAttributeMaxDynamicSharedMemorySize, GEMM_SMEM);
    cudaFuncSetAttribute(flash_mma, cudaFuncAttributeMaxDynamicSharedMemorySize, FLASH_SMEM);

    float*    q;   cudaGetSymbolAddress((void**)&q,   g_Q);
    float*    k;   cudaGetSymbolAddress((void**)&k,   g_K);
    float*    v;   cudaGetSymbolAddress((void**)&v,   g_V);
    uint32_t* xp;  cudaGetSymbolAddress((void**)&xp,  g_Xp);
    uint32_t* yp;  cudaGetSymbolAddress((void**)&yp,  g_Yp);
    uint32_t* wpa; cudaGetSymbolAddress((void**)&wpa, g_Wpa);
    uint32_t* wpp; cudaGetSymbolAddress((void**)&wpp, g_Wpp);
    uint32_t* qp;  cudaGetSymbolAddress((void**)&qp,  g_Qp);
    uint32_t* kp;  cudaGetSymbolAddress((void**)&kp,  g_Kp);
    uint32_t* vp;  cudaGetSymbolAddress((void**)&vp,  g_Vp);

    const int QKV_U4 = (BH * SEQ * HD / 4) / 256;   // 8192 blocks

    // 0) Pack GEMM operands
    pack_a<<<(M_TOK * D_MODEL / 4) / 256, 256>>>(x, xp);
    pack_b<<<(3 * D_MODEL * D_MODEL / 4) / 256, 256>>>(W_attn, wpa, 3 * D_MODEL);
    pack_b<<<(D_MODEL * D_MODEL / 4) / 256, 256>>>(W_proj, wpp, D_MODEL);

    // 1) QKV projection -> g_Q/g_K/g_V (fp32, head-major)
    {
        dim3 grid(3 * D_MODEL / 128, M_TOK / 128);  // (24, 64)
        gemm_mma<1><<<grid, 256, GEMM_SMEM>>>(xp, wpa, b_attn, nullptr);
    }
    // 1.5) Pack Q/K/V into fragment-layout tf32
    pack_q<<<QKV_U4, 256>>>(q, qp);
    pack_k<<<QKV_U4, 256>>>(k, kp);
    pack_v<<<QKV_U4, 256>>>(v, vp);

    // 2) Causal flash attention -> g_Yp (packed tf32)
    {
        dim3 grid(SEQ / QROWS, BH);  // (8, 64)
        flash_mma<<<grid, 256, FLASH_SMEM>>>();
    }
    // 3) Output projection -> d_out
    {
        dim3 grid(D_MODEL / 128, M_TOK / 128);  // (8, 64)
        gemm_mma<0><<<grid, 256, GEMM_SMEM>>>(yp, wpp, b_proj, out);
    }
}

// round 11
// speedup vs baseline: 1.0560x; 1.0001x over previous
#include <cuda_runtime.h>
#include <math.h>
#include <stdint.h>

// Problem constants
#define D_MODEL 1024
#define N_HEADS 16
#define HD      64
#define BATCH   4
#define SEQ     2048
#define BH      (BATCH * N_HEADS)   // 64
#define M_TOK   (BATCH * SEQ)       // 8192

// Scratch (device globals: allocation-free per harness rules)
__device__ float    g_Q[(size_t)BH * SEQ * HD];
__device__ float    g_K[(size_t)BH * SEQ * HD];
__device__ float    g_V[(size_t)BH * SEQ * HD];
__device__ uint32_t g_Xp[(size_t)M_TOK * D_MODEL];        // x, packed tf32 A-frag
__device__ uint32_t g_Yp[(size_t)M_TOK * D_MODEL];        // attn out, packed tf32 A-frag
__device__ uint32_t g_Wpa[(size_t)3 * D_MODEL * D_MODEL]; // W_attn^T packed tf32 B-frag
__device__ uint32_t g_Wpp[(size_t)D_MODEL * D_MODEL];     // W_proj^T packed tf32 B-frag
__device__ uint32_t g_Qp[(size_t)BH * SEQ * HD];          // Q packed tf32 A-frag (scaled)
__device__ uint32_t g_Kp[(size_t)BH * SEQ * HD];          // K packed tf32 B-frag
__device__ uint32_t g_Vp[(size_t)BH * SEQ * HD];          // V packed tf32 B-frag (n=d)

// ---------------------------------------------------------------------------
// Helpers (base-target ISA; sm_80+)
// ---------------------------------------------------------------------------
__device__ __forceinline__ uint32_t f2tf32(float f) {
    uint32_t r;
    asm("cvt.rna.tf32.f32 %0, %1;" : "=r"(r) : "f"(f));
    return r;
}
__device__ __forceinline__ void mma_tf32(float d[4], const uint32_t a[4],
                                         const uint32_t b[2]) {
    asm volatile(
        "mma.sync.aligned.m16n8k8.row.col.f32.tf32.tf32.f32 "
        "{%0,%1,%2,%3}, {%4,%5,%6,%7}, {%8,%9}, {%0,%1,%2,%3};"
        : "+f"(d[0]), "+f"(d[1]), "+f"(d[2]), "+f"(d[3])
        : "r"(a[0]), "r"(a[1]), "r"(a[2]), "r"(a[3]), "r"(b[0]), "r"(b[1]));
}
__device__ __forceinline__ uint32_t smem_u32(const void* p) {
    uint32_t a;
    asm("{ .reg .u64 t; cvta.to.shared.u64 t, %1; cvt.u32.u64 %0, t; }"
        : "=r"(a) : "l"(p));
    return a;
}
#define CP16(dst, src) \
    asm volatile("cp.async.cg.shared.global [%0], [%1], 16;" \
                 :: "r"(dst), "l"(src) : "memory")
#define CPCOMMIT() asm volatile("cp.async.commit_group;" ::: "memory")
#define CPWAIT1()  asm volatile("cp.async.wait_group 1;" ::: "memory")
#define CPWAIT0()  asm volatile("cp.async.wait_group 0;" ::: "memory")

// ---------------------------------------------------------------------------
// GEMM packing kernels (unchanged from Round 8).
// ---------------------------------------------------------------------------
__global__ void pack_a(const float* __restrict__ X, uint32_t* __restrict__ Xp)
{
    const int i    = blockIdx.x * 256 + threadIdx.x;   // uint4 index
    const int lane = i & 31, kc = (i >> 5) & 3, slab = (i >> 7) & 31, mb = i >> 12;
    const int g = lane >> 2, t = lane & 3;
    const float* p = X + ((size_t)(mb * 16 + g)) * D_MODEL + slab * 32 + kc * 8 + t;
    uint4 o;
    o.x = f2tf32(p[0]);
    o.y = f2tf32(p[8 * D_MODEL]);
    o.z = f2tf32(p[4]);
    o.w = f2tf32(p[8 * D_MODEL + 4]);
    *(uint4*)&Xp[(size_t)i * 4] = o;
}

__global__ void pack_b(const float* __restrict__ W, uint32_t* __restrict__ Wp, int N)
{
    const int i    = blockIdx.x * 256 + threadIdx.x;
    const int lane = i & 31, kp = (i >> 5) & 1, slab = (i >> 6) & 31, nb = i >> 11;
    const int g = lane >> 2, t = lane & 3;
    const int n  = nb * 8 + g;
    const int k0 = slab * 32 + kp * 16 + t;
    const float* p = W + (size_t)k0 * N + n;
    uint4 o;
    o.x = f2tf32(p[0]);
    o.y = f2tf32(p[(size_t)4 * N]);
    o.z = f2tf32(p[(size_t)8 * N]);
    o.w = f2tf32(p[(size_t)12 * N]);
    *(uint4*)&Wp[(size_t)i * 4] = o;
}

// ---------------------------------------------------------------------------
// Flash packing kernels: g_Q/g_K/g_V (fp32, head-major) -> fragment-layout tf32.
// Q A-frag (QSCALE folded): uint4 i -> lane(5) | c(3) | mb(4) | qt(3) | bh(6).
//   rows r0 = qt*256 + mb*16 + g, r1 = r0+8; k-chunk 8c.
// K B-frag: uint4 i -> lane(5) | blk(5) | kt(5) | bh(6); nf=blk>>2, kp=blk&3.
//   key = kt*64 + 8nf + g; d = 16kp + t (+4,+8,+12).
// V B-frag (n=d, k=key): d = 8*(blk>>2)+g; key = kt*64 + 16*(blk&3) + t (+4..).
// ---------------------------------------------------------------------------
__global__ void pack_q(const float* __restrict__ Q, uint32_t* __restrict__ Qp)
{
    const float QSCALE = 0.125f * 1.44269504f;
    const int i    = blockIdx.x * 256 + threadIdx.x;
    const int lane = i & 31, c = (i >> 5) & 7, mb = (i >> 8) & 15;
    const int qt   = (i >> 12) & 7, bh = i >> 15;
    const int g = lane >> 2, t = lane & 3;
    const float* r0 = Q + ((size_t)bh * SEQ + qt * 256 + mb * 16 + g) * HD + c * 8;
    const float* r1 = r0 + 8 * HD;
    uint4 o;
    o.x = f2tf32(r0[t]     * QSCALE);
    o.y = f2tf32(r1[t]     * QSCALE);
    o.z = f2tf32(r0[t + 4] * QSCALE);
    o.w = f2tf32(r1[t + 4] * QSCALE);
    *(uint4*)&Qp[(size_t)i * 4] = o;
}

__global__ void pack_k(const float* __restrict__ K, uint32_t* __restrict__ Kp)
{
    const int i    = blockIdx.x * 256 + threadIdx.x;
    const int lane = i & 31, blk = (i >> 5) & 31, kt = (i >> 10) & 31, bh = i >> 15;
    const int g = lane >> 2, t = lane & 3;
    const int nf = blk >> 2, kp = blk & 3;
    const int key = kt * 64 + 8 * nf + g;
    const float* p = K + ((size_t)bh * SEQ + key) * HD + kp * 16 + t;
    uint4 o;
    o.x = f2tf32(p[0]);
    o.y = f2tf32(p[4]);
    o.z = f2tf32(p[8]);
    o.w = f2tf32(p[12]);
    *(uint4*)&Kp[(size_t)i * 4] = o;
}

__global__ void pack_v(const float* __restrict__ V, uint32_t* __restrict__ Vp)
{
    const int i    = blockIdx.x * 256 + threadIdx.x;
    const int lane = i & 31, blk = (i >> 5) & 31, kt = (i >> 10) & 31, bh = i >> 15;
    const int g = lane >> 2, t = lane & 3;
    const int d  = 8 * (blk >> 2) + g;
    const int key0 = kt * 64 + 16 * (blk & 3) + t;
    const float* p = V + ((size_t)bh * SEQ + key0) * HD + d;
    uint4 o;
    o.x = f2tf32(p[0]);
    o.y = f2tf32(p[(size_t)4 * HD]);
    o.z = f2tf32(p[(size_t)8 * HD]);
    o.w = f2tf32(p[(size_t)12 * HD]);
    *(uint4*)&Vp[(size_t)i * 4] = o;
}

// ---------------------------------------------------------------------------
// TF32 GEMM, cp.async 2-stage, packed operands (unchanged from Round 8).
// ---------------------------------------------------------------------------
#define GEMM_SMEM 65536

template <int MODE>
__global__ void __launch_bounds__(256, 2)
gemm_mma(const uint32_t* __restrict__ Apk, const uint32_t* __restrict__ Bpk,
         const float* __restrict__ bias, float* __restrict__ Cout)
{
    constexpr int NS = 32;
    extern __shared__ uint32_t sm[];
    const int tid  = threadIdx.x;
    const int wid  = tid >> 5;
    const int lane = tid & 31;
    const int g    = lane >> 2;
    const int tig  = lane & 3;
    const int m0   = blockIdx.y * 128;
    const int n0   = blockIdx.x * 128;
    const int mb0  = m0 >> 4;
    const int nb0  = n0 >> 3;
    const uint32_t smb = smem_u32(sm);

    float acc[2][8][4];
#pragma unroll
    for (int mf = 0; mf < 2; mf++)
#pragma unroll
        for (int nf = 0; nf < 8; nf++)
#pragma unroll
            for (int r = 0; r < 4; r++) acc[mf][nf][r] = 0.0f;

    uint32_t asrc[4], bsrc[4], adst[4], bdst[4];
#pragma unroll
    for (int c = 0; c < 4; c++) {
        const int ci = c * 256 + tid;
        asrc[c] = (uint32_t)(mb0 + (ci >> 7)) * 16384u + (uint32_t)(ci & 127) * 4u;
        bsrc[c] = (uint32_t)(nb0 + (ci >> 6)) * 8192u  + (uint32_t)(ci & 63) * 4u;
        adst[c] = smb + (uint32_t)ci * 16u;
        bdst[c] = smb + 16384u + (uint32_t)ci * 16u;
    }

    auto issue = [&](int s, int buf) {
        const uint32_t so = (uint32_t)buf * 32768u;
#pragma unroll
        for (int c = 0; c < 4; c++)
            CP16(adst[c] + so, (const void*)(Apk + asrc[c] + (uint32_t)s * 512u));
#pragma unroll
        for (int c = 0; c < 4; c++)
            CP16(bdst[c] + so, (const void*)(Bpk + bsrc[c] + (uint32_t)s * 256u));
        CPCOMMIT();
    };

    issue(0, 0);

    const int wm4 = (wid & 3) * 2;
    const int wn8 = (wid >> 2) * 8;

    for (int s = 0; s < NS; s++) {
        if (s + 1 < NS) { issue(s + 1, (s + 1) & 1); CPWAIT1(); }
        else            { CPWAIT0(); }
        __syncthreads();

        const uint32_t* Ab = sm + (uint32_t)(s & 1) * 8192u;
        const uint32_t* Bb = Ab + 4096;

#pragma unroll
        for (int kp = 0; kp < 2; kp++) {
            uint4 af[2][2];
#pragma unroll
            for (int mf = 0; mf < 2; mf++)
#pragma unroll
                for (int h = 0; h < 2; h++)
                    af[mf][h] = *(const uint4*)&Ab[(((wm4 + mf) * 4 + kp * 2 + h) * 32 + lane) * 4];
#pragma unroll
            for (int nf = 0; nf < 8; nf++) {
                const uint4 bv = *(const uint4*)&Bb[(((wn8 + nf) * 2 + kp) * 32 + lane) * 4];
#pragma unroll
                for (int h = 0; h < 2; h++) {
                    uint32_t b2[2];
                    b2[0] = h ? bv.z : bv.x;
                    b2[1] = h ? bv.w : bv.y;
                    mma_tf32(acc[0][nf], (const uint32_t*)&af[0][h], b2);
                    mma_tf32(acc[1][nf], (const uint32_t*)&af[1][h], b2);
                }
            }
        }
        __syncthreads();
    }

#pragma unroll
    for (int mf = 0; mf < 2; mf++) {
        const int row0 = m0 + (wid & 3) * 32 + mf * 16 + g;
#pragma unroll
        for (int nf = 0; nf < 8; nf++) {
            const int col = n0 + (wid >> 2) * 64 + nf * 8 + 2 * tig;
            const float2 bv = *(const float2*)(bias + col);
            float2 v0 = make_float2(acc[mf][nf][0] + bv.x, acc[mf][nf][1] + bv.y);
            float2 v1 = make_float2(acc[mf][nf][2] + bv.x, acc[mf][nf][3] + bv.y);
            if (MODE == 0) {
                *(float2*)(Cout + (size_t)row0 * D_MODEL + col)       = v0;
                *(float2*)(Cout + (size_t)(row0 + 8) * D_MODEL + col) = v1;
            } else {
                const int which = col >> 10;
                const int c2    = col & 1023;
                const int h     = c2 >> 6;
                const int d     = c2 & 63;
                float* dst = (which == 0) ? g_Q : (which == 1) ? g_K : g_V;
                const int bb0 = row0 >> 11, t0 = row0 & 2047;
                const int r1  = row0 + 8;
                const int bb1 = r1 >> 11,   t1 = r1 & 2047;
                *(float2*)(dst + (((size_t)(bb0 * N_HEADS + h)) * SEQ + t0) * HD + d) = v0;
                *(float2*)(dst + (((size_t)(bb1 * N_HEADS + h)) * SEQ + t1) * HD + d) = v1;
            }
        }
    }
}

// ---------------------------------------------------------------------------
// Flash attention (Round-10): all operands pre-packed tf32 in gmem.
// Q staged once via cp.async (64KB); K/V per 64-key tile via 2-stage cp.async
// pipeline (16KB each, contiguous copies). No cvt / transpose in mainloop.
// Smem: Q 64KB + 2 stages x 32KB = 128KB. Layouts contiguous (stride 128) --
// copy pattern == load pattern, conflict-free.
// ---------------------------------------------------------------------------
#define QROWS 256
#define QP_U32 (QROWS * HD)              // 16384 u32 = 64KB
#define KVT_U32 4096                     // one K or V tile = 16KB
#define FLASH_SMEM ((QP_U32 + 2 * 2 * KVT_U32) * 4)   // 131072

__global__ void __launch_bounds__(256, 1)
flash_mma()
{
    extern __shared__ uint32_t fsm[];
    uint4* Qp4 = (uint4*)fsm;            // packed A-frag
    const uint32_t smb = smem_u32(fsm);

    const int tid  = threadIdx.x;
    const int wid  = tid >> 5;
    const int lane = tid & 31;
    const int g    = lane >> 2;
    const int tig  = lane & 3;
    const int qt   = (int)gridDim.x - 1 - (int)blockIdx.x;
    const int bh   = blockIdx.y;
    const int q0   = qt * QROWS;
    const int nt   = qt * 4 + 4;

    const uint32_t* qg = g_Qp + ((size_t)bh * 8 + qt) * QP_U32;
    const uint32_t* kg = g_Kp + (size_t)bh * 32 * KVT_U32;
    const uint32_t* vg = g_Vp + (size_t)bh * 32 * KVT_U32;

    // Q copy: 16 x CP16 per thread, one group.
#pragma unroll
    for (int c = 0; c < 16; c++)
        CP16(smb + (uint32_t)(c * 256 + tid) * 16u,
             (const void*)(qg + (size_t)(c * 256 + tid) * 4));
    CPCOMMIT();

    auto issueKV = [&](int kt, int buf) {
        const uint32_t so = smb + (uint32_t)(QP_U32 + buf * 2 * KVT_U32) * 4u;
        const uint32_t* ks = kg + (size_t)kt * KVT_U32;
        const uint32_t* vs = vg + (size_t)kt * KVT_U32;
#pragma unroll
        for (int c = 0; c < 4; c++)
            CP16(so + (uint32_t)(c * 256 + tid) * 16u,
                 (const void*)(ks + (size_t)(c * 256 + tid) * 4));
#pragma unroll
        for (int c = 0; c < 4; c++)
            CP16(so + (uint32_t)KVT_U32 * 4u + (uint32_t)(c * 256 + tid) * 16u,
                 (const void*)(vs + (size_t)(c * 256 + tid) * 4));
        CPCOMMIT();
    };

    issueKV(0, 0);

    float mrow[2][2], lrow[2][2], Of[2][8][4];
#pragma unroll
    for (int mf = 0; mf < 2; mf++) {
        mrow[mf][0] = mrow[mf][1] = -1e30f;
        lrow[mf][0] = lrow[mf][1] = 0.0f;
#pragma unroll
        for (int nf = 0; nf < 8; nf++)
#pragma unroll
            for (int r = 0; r < 4; r++) Of[mf][nf][r] = 0.0f;
    }

    for (int kt = 0; kt < nt; kt++) {
        if (kt + 1 < nt) { issueKV(kt + 1, (kt + 1) & 1); CPWAIT1(); }
        else             { CPWAIT0(); }
        __syncthreads();

        const uint32_t* Kps = fsm + QP_U32 + (kt & 1) * 2 * KVT_U32;
        const uint32_t* Vps = Kps + KVT_U32;

        // ---- S = Q K^T ----
        float sacc[2][8][4];
#pragma unroll
        for (int mf = 0; mf < 2; mf++)
#pragma unroll
            for (int nf = 0; nf < 8; nf++)
#pragma unroll
                for (int r = 0; r < 4; r++) sacc[mf][nf][r] = 0.0f;

#pragma unroll
        for (int kp = 0; kp < 4; kp++) {
            uint4 aq[2][2];
#pragma unroll
            for (int mf = 0; mf < 2; mf++)
#pragma unroll
                for (int h = 0; h < 2; h++)
                    aq[mf][h] = Qp4[((wid * 2 + mf) * 8 + kp * 2 + h) * 32 + lane];
#pragma unroll
            for (int half = 0; half < 2; half++) {
                uint4 kb[4];
#pragma unroll
                for (int i = 0; i < 4; i++)
                    kb[i] = *(const uint4*)&Kps[(((half * 4 + i) * 4 + kp) * 32 + lane) * 4];
#pragma unroll
                for (int h = 0; h < 2; h++)
#pragma unroll
                    for (int i = 0; i < 4; i++) {
                        uint32_t b[2];
                        b[0] = h ? kb[i].z : kb[i].x;
                        b[1] = h ? kb[i].w : kb[i].y;
                        mma_tf32(sacc[0][half * 4 + i], (const uint32_t*)&aq[0][h], b);
                        mma_tf32(sacc[1][half * 4 + i], (const uint32_t*)&aq[1][h], b);
                    }
            }
        }

        // Causal mask
        if (kt >= nt - 4) {
            const int n0 = kt * 64;
#pragma unroll
            for (int mf = 0; mf < 2; mf++) {
                const int r0g = q0 + wid * 32 + mf * 16 + g;
#pragma unroll
                for (int nf = 0; nf < 8; nf++) {
                    const int c0 = n0 + nf * 8 + 2 * tig;
                    if (c0     > r0g)     sacc[mf][nf][0] = -1e30f;
                    if (c0 + 1 > r0g)     sacc[mf][nf][1] = -1e30f;
                    if (c0     > r0g + 8) sacc[mf][nf][2] = -1e30f;
                    if (c0 + 1 > r0g + 8) sacc[mf][nf][3] = -1e30f;
                }
            }
        }

        // ---- Online softmax ----
        uint32_t P0[2][8], P1[2][8], P2[2][8], P3[2][8];
#pragma unroll
        for (int mf = 0; mf < 2; mf++) {
            float rm0 = -1e30f, rm1 = -1e30f;
#pragma unroll
            for (int nf = 0; nf < 8; nf++) {
                rm0 = fmaxf(rm0, fmaxf(sacc[mf][nf][0], sacc[mf][nf][1]));
                rm1 = fmaxf(rm1, fmaxf(sacc[mf][nf][2], sacc[mf][nf][3]));
            }
            rm0 = fmaxf(rm0, __shfl_xor_sync(0xffffffffu, rm0, 1));
            rm0 = fmaxf(rm0, __shfl_xor_sync(0xffffffffu, rm0, 2));
            rm1 = fmaxf(rm1, __shfl_xor_sync(0xffffffffu, rm1, 1));
            rm1 = fmaxf(rm1, __shfl_xor_sync(0xffffffffu, rm1, 2));

            const float nm0 = fmaxf(mrow[mf][0], rm0);
            const float nm1 = fmaxf(mrow[mf][1], rm1);
            const float al0 = exp2f(mrow[mf][0] - nm0);
            const float al1 = exp2f(mrow[mf][1] - nm1);
            mrow[mf][0] = nm0; mrow[mf][1] = nm1;

            float rs0 = 0.0f, rs1 = 0.0f;
#pragma unroll
            for (int nf = 0; nf < 8; nf++) {
                const float p0 = exp2f(sacc[mf][nf][0] - nm0);
                const float p1 = exp2f(sacc[mf][nf][1] - nm0);
                const float p2 = exp2f(sacc[mf][nf][2] - nm1);
                const float p3 = exp2f(sacc[mf][nf][3] - nm1);
                rs0 += p0 + p1;
                rs1 += p2 + p3;
                P0[mf][nf] = f2tf32(p0); P1[mf][nf] = f2tf32(p1);
                P2[mf][nf] = f2tf32(p2); P3[mf][nf] = f2tf32(p3);
            }
            rs0 += __shfl_xor_sync(0xffffffffu, rs0, 1);
            rs0 += __shfl_xor_sync(0xffffffffu, rs0, 2);
            rs1 += __shfl_xor_sync(0xffffffffu, rs1, 1);
            rs1 += __shfl_xor_sync(0xffffffffu, rs1, 2);
            lrow[mf][0] = lrow[mf][0] * al0 + rs0;
            lrow[mf][1] = lrow[mf][1] * al1 + rs1;

#pragma unroll
            for (int nf = 0; nf < 8; nf++) {
                Of[mf][nf][0] *= al0; Of[mf][nf][1] *= al0;
                Of[mf][nf][2] *= al1; Of[mf][nf][3] *= al1;
            }
        }

        // ---- O += P V ----
        const int srcA = (lane & 28) | (tig >> 1);
        const int srcB = srcA + 2;
        const bool hi  = (tig & 1);
#pragma unroll
        for (int kp = 0; kp < 4; kp++) {
            uint32_t ap[2][2][4];
#pragma unroll
            for (int mf = 0; mf < 2; mf++)
#pragma unroll
                for (int h = 0; h < 2; h++) {
                    const int kc = kp * 2 + h;
                    uint32_t x0 = __shfl_sync(0xffffffffu, P0[mf][kc], srcA);
                    uint32_t x1 = __shfl_sync(0xffffffffu, P1[mf][kc], srcA);
                    uint32_t y0 = __shfl_sync(0xffffffffu, P2[mf][kc], srcA);
                    uint32_t y1 = __shfl_sync(0xffffffffu, P3[mf][kc], srcA);
                    uint32_t z0 = __shfl_sync(0xffffffffu, P0[mf][kc], srcB);
                    uint32_t z1 = __shfl_sync(0xffffffffu, P1[mf][kc], srcB);
                    uint32_t w0 = __shfl_sync(0xffffffffu, P2[mf][kc], srcB);
                    uint32_t w1 = __shfl_sync(0xffffffffu, P3[mf][kc], srcB);
                    ap[mf][h][0] = hi ? x1 : x0;
                    ap[mf][h][1] = hi ? y1 : y0;
                    ap[mf][h][2] = hi ? z1 : z0;
                    ap[mf][h][3] = hi ? w1 : w0;
                }
#pragma unroll
            for (int half = 0; half < 2; half++) {
                uint4 vb[4];
#pragma unroll
                for (int i = 0; i < 4; i++)
                    vb[i] = *(const uint4*)&Vps[(((half * 4 + i) * 4 + kp) * 32 + lane) * 4];
#pragma unroll
                for (int h = 0; h < 2; h++)
#pragma unroll
                    for (int i = 0; i < 4; i++) {
                        uint32_t b[2];
                        b[0] = h ? vb[i].z : vb[i].x;
                        b[1] = h ? vb[i].w : vb[i].y;
                        mma_tf32(Of[0][half * 4 + i], ap[0][h], b);
                        mma_tf32(Of[1][half * 4 + i], ap[1][h], b);
                    }
            }
        }
        __syncthreads();   // all fragment reads done before buffer reuse
    }

    // Epilogue: write packed tf32 A-fragment g_Yp (quad-shuffle transform).
    const int b = bh >> 4;
    const int h = bh & 15;
    const int srcA = (lane & 28) | (tig >> 1);
    const int srcB = srcA + 2;
    const bool hi  = (tig & 1);
#pragma unroll
    for (int mf = 0; mf < 2; mf++) {
        const float inv0 = 1.0f / lrow[mf][0];
        const float inv1 = 1.0f / lrow[mf][1];
        const int mb = (b * SEQ + q0 + wid * 32 + mf * 16) >> 4;
#pragma unroll
        for (int j = 0; j < 8; j++) {
            const float n0f = Of[mf][j][0] * inv0;
            const float n1f = Of[mf][j][1] * inv0;
            const float n2f = Of[mf][j][2] * inv1;
            const float n3f = Of[mf][j][3] * inv1;
            const float x0 = __shfl_sync(0xffffffffu, n0f, srcA);
            const float x1 = __shfl_sync(0xffffffffu, n1f, srcA);
            const float y0 = __shfl_sync(0xffffffffu, n2f, srcA);
            const float y1 = __shfl_sync(0xffffffffu, n3f, srcA);
            const float z0 = __shfl_sync(0xffffffffu, n0f, srcB);
            const float z1 = __shfl_sync(0xffffffffu, n1f, srcB);
            const float w0 = __shfl_sync(0xffffffffu, n2f, srcB);
            const float w1 = __shfl_sync(0xffffffffu, n3f, srcB);
            uint4 o;
            o.x = f2tf32(hi ? x1 : x0);
            o.y = f2tf32(hi ? y1 : y0);
            o.z = f2tf32(hi ? z1 : z0);
            o.w = f2tf32(hi ? w1 : w0);
            const int slab = 2 * h + (j >> 2);
            const int kc   = j & 3;
            *(uint4*)&g_Yp[(((size_t)mb * 32 + slab) * 4 + kc) * 128 + lane * 4] = o;
        }
    }
}

// ---------------------------------------------------------------------------
extern "C" void kernel_launch(void* const* d_in, const int* in_sizes, int n_in,
                              void* d_out, int out_size)
{
    const float* x      = (const float*)d_in[0];
    const float* W_attn = (const float*)d_in[1];
    const float* b_attn = (const float*)d_in[2];
    const float* W_proj = (const float*)d_in[3];
    const float* b_proj = (const float*)d_in[4];
    float* out = (float*)d_out;

    cudaFuncSetAttribute(gemm_mma<1>, cudaFuncAttributeMaxDynamicSharedMemorySize, GEMM_SMEM);
    cudaFuncSetAttribute(gemm_mma<0>, cudaFuncAttributeMaxDynamicSharedMemorySize, GEMM_SMEM);
    cudaFuncSetAttribute(flash_mma, cudaFuncAttributeMaxDynamicSharedMemorySize, FLASH_SMEM);

    float*    q;   cudaGetSymbolAddress((void**)&q,   g_Q);
    float*    k;   cudaGetSymbolAddress((void**)&k,   g_K);
    float*    v;   cudaGetSymbolAddress((void**)&v,   g_V);
    uint32_t* xp;  cudaGetSymbolAddress((void**)&xp,  g_Xp);
    uint32_t* yp;  cudaGetSymbolAddress((void**)&yp,  g_Yp);
    uint32_t* wpa; cudaGetSymbolAddress((void**)&wpa, g_Wpa);
    uint32_t* wpp; cudaGetSymbolAddress((void**)&wpp, g_Wpp);
    uint32_t* qp;  cudaGetSymbolAddress((void**)&qp,  g_Qp);
    uint32_t* kp;  cudaGetSymbolAddress((void**)&kp,  g_Kp);
    uint32_t* vp;  cudaGetSymbolAddress((void**)&vp,  g_Vp);

    const int QKV_U4 = (BH * SEQ * HD / 4) / 256;   // 8192 blocks

    // 0) Pack GEMM operands
    pack_a<<<(M_TOK * D_MODEL / 4) / 256, 256>>>(x, xp);
    pack_b<<<(3 * D_MODEL * D_MODEL / 4) / 256, 256>>>(W_attn, wpa, 3 * D_MODEL);
    pack_b<<<(D_MODEL * D_MODEL / 4) / 256, 256>>>(W_proj, wpp, D_MODEL);

    // 1) QKV projection -> g_Q/g_K/g_V (fp32, head-major)
    {
        dim3 grid(3 * D_MODEL / 128, M_TOK / 128);  // (24, 64)
        gemm_mma<1><<<grid, 256, GEMM_SMEM>>>(xp, wpa, b_attn, nullptr);
    }
    // 1.5) Pack Q/K/V into fragment-layout tf32
    pack_q<<<QKV_U4, 256>>>(q, qp);
    pack_k<<<QKV_U4, 256>>>(k, kp);
    pack_v<<<QKV_U4, 256>>>(v, vp);

    // 2) Causal flash attention -> g_Yp (packed tf32)
    {
        dim3 grid(SEQ / QROWS, BH);  // (8, 64)
        flash_mma<<<grid, 256, FLASH_SMEM>>>();
    }
    // 3) Output projection -> d_out
    {
        dim3 grid(D_MODEL / 128, M_TOK / 128);  // (8, 64)
        gemm_mma<0><<<grid, 256, GEMM_SMEM>>>(yp, wpp, b_proj, out);
    }
}